// round 8
// baseline (speedup 1.0000x reference)
#include <cuda_runtime.h>

#define TT 100
#define FF 3
#define BM 64
#define NTHR 256
#define MAXB 16384

// ---------------- scratch (static __device__, no allocations) ----------------
__device__ int g_len[MAXB];
__device__ int g_perm[MAXB];
__device__ int g_hist[101];
__device__ int g_cur[101];

// ---------------- helpers ----------------
__device__ __forceinline__ unsigned long long pack2(float x, float y){
    unsigned long long r; asm("mov.b64 %0, {%1, %2};" : "=l"(r) : "f"(x), "f"(y)); return r;
}
__device__ __forceinline__ void unpack2(unsigned long long v, float &x, float &y){
    asm("mov.b64 {%0, %1}, %2;" : "=f"(x), "=f"(y) : "l"(v));
}
// packed f32x2 FMA: d = a*b + d  (two fp32 lanes per instruction)
__device__ __forceinline__ void ffma2(unsigned long long &d, unsigned long long a, unsigned long long b){
    asm("fma.rn.f32x2 %0, %1, %2, %0;" : "+l"(d) : "l"(a), "l"(b));
}
__device__ __forceinline__ float sigmoidf_(float x){
    return __fdividef(1.f, 1.f + __expf(-x));
}
__device__ __forceinline__ float tanhf_(float x){
    float ax = fabsf(x);
    float e  = __expf(-2.f * ax);
    float r  = __fdividef(1.f - e, 1.f + e);
    return copysignf(r, x);
}

// ---------------- prepass: lengths + counting sort (longest-first) ----------------
__global__ void k_hist_zero(){
    int i = threadIdx.x;
    if (i < 101) g_hist[i] = 0;
}

__global__ void k_len(const float* __restrict__ x, int B){
    int row = blockIdx.x * blockDim.x + threadIdx.x;
    if (row >= B) return;
    const float* p = x + (size_t)row * (TT * FF);
    int len = 0;
    for (int t = TT - 1; t >= 0; --t){
        float a = p[t*3], b = p[t*3+1], c = p[t*3+2];
        if (a != 0.f || b != 0.f || c != 0.f){ len = t + 1; break; }
    }
    g_len[row] = len;
    atomicAdd(&g_hist[len], 1);
}

__global__ void k_prefix(){
    if (threadIdx.x == 0 && blockIdx.x == 0){
        int run = 0;
        for (int l = 100; l >= 0; --l){ g_cur[l] = run; run += g_hist[l]; }
    }
}

__global__ void k_scatter(int B){
    int row = blockIdx.x * blockDim.x + threadIdx.x;
    if (row >= B) return;
    int p = atomicAdd(&g_cur[g_len[row]], 1);
    g_perm[p] = row;
}

// ---------------- smem layout (bytes) ----------------
#define OFF_UPK   0        // float2[64*4*32]        = 65536  (U packed: (k,gate,cg) -> {U[k][g*64+cg], U[k][g*64+cg+32]})
#define OFF_HD    65536    // u64[64*64]             = 32768  (h duplicated pairs, [row][unit])
#define OFF_XS    98304    // float4[64]             = 1024   (x0,x1,x2,mask)
#define OFF_WB    99328    // float[1024]            = 4096   (W rows 0..2, then b)
#define OFF_RID   103424   // int[64]
#define OFF_MISC  103680   // int[4]
#define SMEM_BYTES 103936
// head aliases the Upk region after the time loop:
#define OFF_W1S   0        // float[64*64] = 16384
#define OFF_H1S   16384    // float[64*65] = 16640 (padded rows, conflict-free)
#define OFF_B1S   33024    // float[64]
#define OFF_W2S   33280    // float[320]
#define OFF_B2S   34560    // float[8]

extern __shared__ char smem[];

__global__ void __launch_bounds__(NTHR, 1)
k_lstm(const float* __restrict__ x,
       const float* __restrict__ W,  const float* __restrict__ U,
       const float* __restrict__ b,
       const float* __restrict__ W1, const float* __restrict__ b1,
       const float* __restrict__ W2, const float* __restrict__ b2,
       float* __restrict__ out)
{
    float2*             Upk  = (float2*)(smem + OFF_UPK);
    unsigned long long* HD   = (unsigned long long*)(smem + OFF_HD);
    float4*             XS   = (float4*)(smem + OFF_XS);
    float*              WB   = (float*)(smem + OFF_WB);
    int*                RID  = (int*)(smem + OFF_RID);
    int*                MISC = (int*)(smem + OFF_MISC);

    const int tid = threadIdx.x;
    const int cg  = tid & 31;       // column group: units cg and cg+32 of each gate
    const int rg  = tid >> 5;       // row group: rows rg*8 .. rg*8+7
    const int r0  = rg * 8;

    // ---- stage U (packed), W/b; zero h ----
    for (int i = tid; i < 64*4*32; i += NTHR){
        int c = i & 31; int gk = i >> 5; int g = gk & 3; int k = gk >> 2;
        Upk[i] = make_float2(U[k*256 + g*64 + c], U[k*256 + g*64 + c + 32]);
    }
    for (int i = tid; i < 768; i += NTHR) WB[i] = W[i];
    for (int i = tid; i < 256; i += NTHR) WB[768 + i] = b[i];
    for (int i = tid; i < 64*64; i += NTHR) HD[i] = 0ull;
    if (tid == 0) MISC[0] = 0;

    int myrow = 0;
    if (tid < BM){ myrow = g_perm[blockIdx.x * BM + tid]; RID[tid] = myrow; }
    __syncthreads();
    if (tid < BM) atomicMax(&MISC[0], g_len[myrow]);
    __syncthreads();
    const int maxlen = MISC[0];

    float c0[8], c1[8];
    #pragma unroll
    for (int i = 0; i < 8; ++i){ c0[i] = 0.f; c1[i] = 0.f; }

    const float* xptr = x + (size_t)((tid < BM) ? myrow : 0) * (TT * FF);

    for (int t = 0; t < maxlen; ++t){
        // issue x loads early — hidden under the GEMM
        float lx0 = 0.f, lx1 = 0.f, lx2 = 0.f;
        if (tid < BM){ lx0 = xptr[t*3]; lx1 = xptr[t*3+1]; lx2 = xptr[t*3+2]; }

        // ---- z = h @ U  (f32x2: each accumulator is a (unit cg, unit cg+32) pair) ----
        unsigned long long z[4][8];
        #pragma unroll
        for (int g = 0; g < 4; ++g)
            #pragma unroll
            for (int ri = 0; ri < 8; ++ri) z[g][ri] = 0ull;

        #pragma unroll 1
        for (int kb = 0; kb < 64; kb += 8){
            #pragma unroll
            for (int kk = 0; kk < 8; ++kk){
                const int k = kb + kk;
                const unsigned long long u0 = *(const unsigned long long*)&Upk[(k*4 + 0)*32 + cg];
                const unsigned long long u1 = *(const unsigned long long*)&Upk[(k*4 + 1)*32 + cg];
                const unsigned long long u2 = *(const unsigned long long*)&Upk[(k*4 + 2)*32 + cg];
                const unsigned long long u3 = *(const unsigned long long*)&Upk[(k*4 + 3)*32 + cg];
                #pragma unroll
                for (int ri = 0; ri < 8; ++ri){
                    const unsigned long long hd = HD[(r0 + ri)*64 + k];  // broadcast (h,h)
                    ffma2(z[0][ri], hd, u0);
                    ffma2(z[1][ri], hd, u1);
                    ffma2(z[2][ri], hd, u2);
                    ffma2(z[3][ri], hd, u3);
                }
            }
        }
        __syncthreads();                       // (A) all HD reads done
        if (tid < BM){
            int m = (lx0 != 0.f) || (lx1 != 0.f) || (lx2 != 0.f);
            XS[tid] = make_float4(lx0, lx1, lx2, m ? 1.f : 0.f);
        }
        __syncthreads();                       // (B) XS visible

        // hoist x-projection weights for this thread's 8 columns
        float wx0[4][2], wx1[4][2], wx2[4][2], wbb[4][2];
        #pragma unroll
        for (int g = 0; g < 4; ++g){
            #pragma unroll
            for (int up = 0; up < 2; ++up){
                const int col = g*64 + up*32 + cg;
                wx0[g][up] = WB[col];
                wx1[g][up] = WB[256 + col];
                wx2[g][up] = WB[512 + col];
                wbb[g][up] = WB[768 + col];
            }
        }

        // ---- gates + state update (mask is uniform across the warp: rows depend only on rg) ----
        #pragma unroll
        for (int ri = 0; ri < 8; ++ri){
            const int r = r0 + ri;
            const float4 xv = XS[r];
            if (xv.w != 0.f){
                float zv[4][2];
                #pragma unroll
                for (int g = 0; g < 4; ++g){
                    float a, bv; unpack2(z[g][ri], a, bv);
                    zv[g][0] = a; zv[g][1] = bv;
                }
                #pragma unroll
                for (int up = 0; up < 2; ++up){
                    float zi = zv[0][up] + wbb[0][up] + xv.x*wx0[0][up] + xv.y*wx1[0][up] + xv.z*wx2[0][up];
                    float zf = zv[1][up] + wbb[1][up] + xv.x*wx0[1][up] + xv.y*wx1[1][up] + xv.z*wx2[1][up];
                    float zg = zv[2][up] + wbb[2][up] + xv.x*wx0[2][up] + xv.y*wx1[2][up] + xv.z*wx2[2][up];
                    float zo = zv[3][up] + wbb[3][up] + xv.x*wx0[3][up] + xv.y*wx1[3][up] + xv.z*wx2[3][up];
                    const float ig = sigmoidf_(zi);
                    const float fg = sigmoidf_(zf);
                    const float og = sigmoidf_(zo);
                    const float gg = tanhf_(zg);
                    const float cprev = up ? c1[ri] : c0[ri];
                    const float cn = fg * cprev + ig * gg;
                    const float hn = og * tanhf_(cn);
                    if (up) c1[ri] = cn; else c0[ri] = cn;
                    HD[r*64 + cg + up*32] = pack2(hn, hn);
                }
            }
        }
        __syncthreads();                       // (C) HD ready for next step
    }

    // ---------------- head: relu(h@W1+b1) @ W2 + b2 -> softmax ----------------
    __syncthreads();
    float* W1S = (float*)(smem + OFF_W1S);
    float* H1S = (float*)(smem + OFF_H1S);
    float* B1S = (float*)(smem + OFF_B1S);
    float* W2S = (float*)(smem + OFF_W2S);
    float* B2S = (float*)(smem + OFF_B2S);
    for (int i = tid; i < 4096; i += NTHR) W1S[i] = W1[i];
    for (int i = tid; i < 64;   i += NTHR) B1S[i] = b1[i];
    for (int i = tid; i < 320;  i += NTHR) W2S[i] = W2[i];
    for (int i = tid; i < 5;    i += NTHR) B2S[i] = b2[i];
    __syncthreads();

    {   // h1: 4 threads per row, 16 outputs each
        const int r = tid >> 2, part = tid & 3;
        float acc[16];
        #pragma unroll
        for (int j = 0; j < 16; ++j) acc[j] = 0.f;
        for (int k = 0; k < 64; ++k){
            const float hk = *(const float*)&HD[r*64 + k];   // low lane of (h,h)
            const float* wr = W1S + k*64 + part*16;
            #pragma unroll
            for (int j = 0; j < 16; ++j) acc[j] += hk * wr[j];
        }
        #pragma unroll
        for (int j = 0; j < 16; ++j){
            float v = acc[j] + B1S[part*16 + j];
            H1S[r*65 + part*16 + j] = v > 0.f ? v : 0.f;
        }
    }
    __syncthreads();

    if (tid < BM){
        float lg[5];
        #pragma unroll
        for (int q = 0; q < 5; ++q) lg[q] = B2S[q];
        for (int k = 0; k < 64; ++k){
            const float v = H1S[tid*65 + k];
            #pragma unroll
            for (int q = 0; q < 5; ++q) lg[q] += v * W2S[k*5 + q];
        }
        float mx = lg[0];
        #pragma unroll
        for (int q = 1; q < 5; ++q) mx = fmaxf(mx, lg[q]);
        float e[5], s = 0.f;
        #pragma unroll
        for (int q = 0; q < 5; ++q){ e[q] = __expf(lg[q] - mx); s += e[q]; }
        const float inv = __fdividef(1.f, s);
        const int grow = RID[tid];
        #pragma unroll
        for (int q = 0; q < 5; ++q) out[grow*5 + q] = e[q] * inv;
    }
}

// ---------------- launch ----------------
extern "C" void kernel_launch(void* const* d_in, const int* in_sizes, int n_in,
                              void* d_out, int out_size)
{
    // robust input mapping by element count (all sizes are distinct)
    const float *x=0, *W=0, *U=0, *b=0, *W1=0, *b1=0, *W2=0, *b2=0;
    int xsize = 0;
    for (int i = 0; i < n_in; ++i){
        const float* p = (const float*)d_in[i];
        switch (in_sizes[i]){
            case 768:    W  = p; break;
            case 16384:  U  = p; break;
            case 256:    b  = p; break;
            case 4096:   W1 = p; break;
            case 64:     b1 = p; break;
            case 320:    W2 = p; break;
            case 5:      b2 = p; break;
            default:     x  = p; xsize = in_sizes[i]; break;  // the big one
        }
    }
    float* out = (float*)d_out;
    const int B = xsize / (TT * FF);   // 16384

    cudaFuncSetAttribute(k_lstm, cudaFuncAttributeMaxDynamicSharedMemorySize, SMEM_BYTES);

    k_hist_zero<<<1, 128>>>();
    k_len<<<(B + 255) / 256, 256>>>(x, B);
    k_prefix<<<1, 32>>>();
    k_scatter<<<(B + 255) / 256, 256>>>(B);
    k_lstm<<<B / BM, NTHR, SMEM_BYTES>>>(x, W, U, b, W1, b1, W2, b2, out);
}